// round 16
// baseline (speedup 1.0000x reference)
#include <cuda_runtime.h>
#include <cuda_fp16.h>
#include <math.h>

#define D_MODEL  1024
#define N_HEADS  16
#define HEAD_DIM 64
#define BATCH    4
#define SEQ      2048
#define M_TOTAL  (BATCH * SEQ)   // 8192
#define GK 1024
#define GN 1024

// ---------------------------------------------------------------------------
// Scratch (fp16; k-dims stored permuted per 16-group: j=8h+2q+e -> 4q+2h+e)
// Wq pre-scaled by 0.125*log2(e): base-2 softmax with no scale multiply.
// ---------------------------------------------------------------------------
__device__ __align__(256) __half g_xt [(size_t)M_TOTAL * D_MODEL];
__device__ __align__(256) __half g_Wqt[(size_t)D_MODEL * D_MODEL];
__device__ __align__(256) __half g_Wkt[(size_t)D_MODEL * D_MODEL];
__device__ __align__(256) __half g_Wvt[(size_t)D_MODEL * D_MODEL];
__device__ __align__(256) __half g_Wot[(size_t)D_MODEL * D_MODEL];
__device__ __align__(256) __half g_Q  [(size_t)M_TOTAL * D_MODEL];  // [B,H,T,Dh] d-perm (pre-scaled)
__device__ __align__(256) __half g_K  [(size_t)M_TOTAL * D_MODEL];  // [B,H,T,Dh] d-perm
__device__ __align__(256) __half g_Vt [(size_t)M_TOTAL * D_MODEL];  // [B,H,Dh,T] t-perm
__device__ __align__(256) __half g_Y  [(size_t)M_TOTAL * D_MODEL];  // [B,T,D] D-perm

#define QSCALE (0.125f * 1.4426950408889634f)

// ---------------------------------------------------------------------------
// helpers
// ---------------------------------------------------------------------------
__device__ __forceinline__ unsigned f2h2(float lo, float hi) {
    __half2 h = __floats2half2_rn(lo, hi);
    return *(unsigned*)&h;
}
__device__ __forceinline__ unsigned short f2h(float v) {
    __half h = __float2half_rn(v);
    return *(unsigned short*)&h;
}

__device__ __forceinline__ void mma_f16(float c[4],
    unsigned a0, unsigned a1, unsigned a2, unsigned a3,
    unsigned b0, unsigned b1)
{
    asm volatile(
        "mma.sync.aligned.m16n8k16.row.col.f32.f16.f16.f32 "
        "{%0,%1,%2,%3}, {%4,%5,%6,%7}, {%8,%9}, {%0,%1,%2,%3};"
        : "+f"(c[0]), "+f"(c[1]), "+f"(c[2]), "+f"(c[3])
        : "r"(a0), "r"(a1), "r"(a2), "r"(a3), "r"(b0), "r"(b1));
}

__device__ __forceinline__ void cpa16(unsigned saddr, const void* gptr) {
    asm volatile("cp.async.cg.shared.global [%0], [%1], 16;"
                 :: "r"(saddr), "l"(gptr));
}

// ---------------------------------------------------------------------------
// fp32 -> fp16 + k-permute, fused over x + 4 weights (one launch).
// ---------------------------------------------------------------------------
#define XN4 (M_TOTAL * D_MODEL / 4)
#define WN4 (D_MODEL * D_MODEL / 4)

__device__ __forceinline__ void cvt_one(const float4* __restrict__ src,
                                        unsigned* __restrict__ dst, int i, float s)
{
    float4 v = src[i];
    int wi = i * 4;
    int h2 = ((wi & ~15) >> 1) + 2 * ((wi >> 1) & 3) + ((wi >> 3) & 1);
    dst[h2]     = f2h2(v.x * s, v.y * s);
    dst[h2 + 2] = f2h2(v.z * s, v.w * s);
}

__global__ void cvt_all_kernel(
    const float4* __restrict__ x,  unsigned* __restrict__ xt,
    const float4* __restrict__ w0, unsigned* __restrict__ t0,
    const float4* __restrict__ w1, unsigned* __restrict__ t1,
    const float4* __restrict__ w2, unsigned* __restrict__ t2,
    const float4* __restrict__ w3, unsigned* __restrict__ t3)
{
    int i = blockIdx.x * blockDim.x + threadIdx.x;
    if (i < XN4) { cvt_one(x, xt, i, 1.0f); return; }
    int j = i - XN4;
    int wsel = j >> 18;
    int r    = j & (WN4 - 1);
    if      (wsel == 0) cvt_one(w0, t0, r, QSCALE);
    else if (wsel == 1) cvt_one(w1, t1, r, 1.0f);
    else if (wsel == 2) cvt_one(w2, t2, r, 1.0f);
    else                cvt_one(w3, t3, r, 1.0f);
}

// ---------------------------------------------------------------------------
// QKV GEMM: BM=128, BN=64, BK=64; 128 threads = 4 warps (2m x 2n).
// 2-stage cp.async, single barrier per iter; 61.4 KB smem -> 3 CTAs/SM.
// ---------------------------------------------------------------------------
#define Q_P   80
#define Q_AH  (128 * Q_P)
#define Q_BH  (64 * Q_P)
#define Q_SH  (Q_AH + Q_BH)
#define Q_SMEM (2 * Q_SH * 2)
#define Q_ITERS (GK / 64)
#define Q_THREADS 128

__global__ void __launch_bounds__(Q_THREADS, 3) gemm_qkv_kernel(
    const __half* __restrict__ A,
    const __half* __restrict__ B0, const float* __restrict__ bias0, __half* __restrict__ C0,
    const __half* __restrict__ B1, const float* __restrict__ bias1, __half* __restrict__ C1,
    const __half* __restrict__ B2, const float* __restrict__ bias2, __half* __restrict__ C2)
{
    extern __shared__ __align__(128) __half smh[];
    const int z = blockIdx.z;
    const __half* B    = (z == 0) ? B0    : (z == 1) ? B1    : B2;
    const float* bias  = (z == 0) ? bias0 : (z == 1) ? bias1 : bias2;
    __half*      C     = (z == 0) ? C0    : (z == 1) ? C1    : C2;
    const float bscale = (z == 0) ? QSCALE : 1.0f;

    const int tid  = threadIdx.x;
    const int lane = tid & 31;
    const int w    = tid >> 5;
    const int wm   = w >> 1;
    const int wn   = w & 1;
    const int g    = lane >> 2;
    const int q    = lane & 3;
    const int bm   = blockIdx.y;
    const int bn   = blockIdx.x;

    const __half* Ab = A + (size_t)bm * 128 * GK;
    const __half* Bb = B + (size_t)bn * 64 * GK;
    const unsigned sb = (unsigned)__cvta_generic_to_shared(smh);

    float acc[4][4][4];
#pragma unroll
    for (int mt = 0; mt < 4; mt++)
#pragma unroll
        for (int nt = 0; nt < 4; nt++)
#pragma unroll
            for (int i = 0; i < 4; i++) acc[mt][nt][i] = 0.0f;

#define Q_FILL(S, KC)                                                        \
    {                                                                        \
        unsigned abase = sb + (unsigned)(S) * (Q_SH * 2);                    \
        unsigned bbase = abase + (Q_AH * 2);                                 \
        _Pragma("unroll")                                                    \
        for (int i = 0; i < 8; i++) {                                        \
            int idx = i * Q_THREADS + tid;                                   \
            int r = idx >> 3, c8 = idx & 7;                                  \
            cpa16(abase + (unsigned)(r * Q_P + c8 * 8) * 2u,                 \
                  Ab + (size_t)r * GK + (KC) * 64 + c8 * 8);                 \
        }                                                                    \
        _Pragma("unroll")                                                    \
        for (int i = 0; i < 4; i++) {                                        \
            int idx = i * Q_THREADS + tid;                                   \
            int r = idx >> 3, c8 = idx & 7;                                  \
            cpa16(bbase + (unsigned)(r * Q_P + c8 * 8) * 2u,                 \
                  Bb + (size_t)r * GK + (KC) * 64 + c8 * 8);                 \
        }                                                                    \
    }

    Q_FILL(0, 0);
    asm volatile("cp.async.commit_group;" ::: "memory");

    for (int it = 0; it < Q_ITERS; it++) {
        const int buf = it & 1;
        asm volatile("cp.async.wait_group 0;" ::: "memory");
        __syncthreads();
        if (it + 1 < Q_ITERS) {
            Q_FILL(buf ^ 1, it + 1);
        }
        asm volatile("cp.async.commit_group;" ::: "memory");

        const __half* As = smh + buf * Q_SH;
        const __half* Bs = As + Q_AH;

#pragma unroll
        for (int ks = 0; ks < 4; ks++) {
            uint2 af[4][2];
            uint2 bf[4];
#pragma unroll
            for (int mt = 0; mt < 4; mt++) {
                int r = wm * 64 + mt * 16 + g;
                af[mt][0] = *(const uint2*)(As + r * Q_P + ks * 16 + 4 * q);
                af[mt][1] = *(const uint2*)(As + (r + 8) * Q_P + ks * 16 + 4 * q);
            }
#pragma unroll
            for (int nt = 0; nt < 4; nt++) {
                int c = wn * 32 + nt * 8 + g;
                bf[nt] = *(const uint2*)(Bs + c * Q_P + ks * 16 + 4 * q);
            }
#pragma unroll
            for (int mt = 0; mt < 4; mt++)
#pragma unroll
                for (int nt = 0; nt < 4; nt++)
                    mma_f16(acc[mt][nt],
                            af[mt][0].x, af[mt][1].x,
                            af[mt][0].y, af[mt][1].y,
                            bf[nt].x,    bf[nt].y);
        }
    }
#undef Q_FILL

    const int h = bn;
#pragma unroll
    for (int mt = 0; mt < 4; mt++) {
        int m0 = bm * 128 + wm * 64 + mt * 16 + g;
        int m1 = m0 + 8;
        int bb0 = m0 / SEQ, t0 = m0 % SEQ;
        int bb1 = m1 / SEQ, t1 = m1 % SEQ;
#pragma unroll
        for (int nt = 0; nt < 4; nt++) {
            int nb = wn * 32 + nt * 8;
            int n0 = bn * 64 + nb + 2 * q;
            float b0 = bias[n0] * bscale, b1 = bias[n0 + 1] * bscale;
            float v00 = acc[mt][nt][0] + b0;
            float v01 = acc[mt][nt][1] + b1;
            float v10 = acc[mt][nt][2] + b0;
            float v11 = acc[mt][nt][3] + b1;
            if (z != 2) {
                int slot = (nb & ~15) + 4 * q + 2 * (nt & 1);
                size_t r0o = (((size_t)(bb0 * N_HEADS + h) * SEQ) + t0) * HEAD_DIM;
                size_t r1o = (((size_t)(bb1 * N_HEADS + h) * SEQ) + t1) * HEAD_DIM;
                *(unsigned*)(C + r0o + slot) = f2h2(v00, v01);
                *(unsigned*)(C + r1o + slot) = f2h2(v10, v11);
            } else {
                int d0 = nb + 2 * q;
                int t0p = (t0 & ~15) + 4 * (g >> 1) + (g & 1);
                int t1p = (t1 & ~15) + 4 * (g >> 1) + 2 + (g & 1);
                size_t base0 = ((size_t)(bb0 * N_HEADS + h) * HEAD_DIM + d0) * SEQ;
                size_t base1 = ((size_t)(bb1 * N_HEADS + h) * HEAD_DIM + d0) * SEQ;
                ((unsigned short*)C)[base0 + t0p]       = f2h(v00);
                ((unsigned short*)C)[base0 + SEQ + t0p] = f2h(v01);
                ((unsigned short*)C)[base1 + t1p]       = f2h(v10);
                ((unsigned short*)C)[base1 + SEQ + t1p] = f2h(v11);
            }
        }
    }
}

// ---------------------------------------------------------------------------
// O-proj GEMM: BM=128, BN=128, 256 threads, 2-stage, single barrier,
// 80 KB smem -> 2 CTAs/SM. fp32 [M,N] output.
// ---------------------------------------------------------------------------
#define G_P   80
#define G_AH  (128 * G_P)
#define G_BH  (128 * G_P)
#define G_SH  (G_AH + G_BH)
#define G_SMEM (2 * G_SH * 2)
#define G_ITERS (GK / 64)
#define G_THREADS 256

__global__ void __launch_bounds__(G_THREADS, 2) gemm_o_kernel(
    const __half* __restrict__ A, const __half* __restrict__ B,
    const float* __restrict__ bias, float* __restrict__ C)
{
    extern __shared__ __align__(128) __half smh[];

    const int tid  = threadIdx.x;
    const int lane = tid & 31;
    const int w    = tid >> 5;
    const int wm   = w >> 2;
    const int wn   = w & 3;
    const int g    = lane >> 2;
    const int q    = lane & 3;
    const int bm   = blockIdx.y;
    const int bn   = blockIdx.x;

    const __half* Ab = A + (size_t)bm * 128 * GK;
    const __half* Bb = B + (size_t)bn * 128 * GK;
    const unsigned sb = (unsigned)__cvta_generic_to_shared(smh);

    float acc[4][4][4];
#pragma unroll
    for (int mt = 0; mt < 4; mt++)
#pragma unroll
        for (int nt = 0; nt < 4; nt++)
#pragma unroll
            for (int i = 0; i < 4; i++) acc[mt][nt][i] = 0.0f;

#define G_FILL(S, KC)                                                        \
    {                                                                        \
        unsigned abase = sb + (unsigned)(S) * (G_SH * 2);                    \
        unsigned bbase = abase + (G_AH * 2);                                 \
        _Pragma("unroll")                                                    \
        for (int i = 0; i < 4; i++) {                                        \
            int idx = i * G_THREADS + tid;                                   \
            int r = idx >> 3, c8 = idx & 7;                                  \
            cpa16(abase + (unsigned)(r * G_P + c8 * 8) * 2u,                 \
                  Ab + (size_t)r * GK + (KC) * 64 + c8 * 8);                 \
        }                                                                    \
        _Pragma("unroll")                                                    \
        for (int i = 0; i < 4; i++) {                                        \
            int idx = i * G_THREADS + tid;                                   \
            int r = idx >> 3, c8 = idx & 7;                                  \
            cpa16(bbase + (unsigned)(r * G_P + c8 * 8) * 2u,                 \
                  Bb + (size_t)r * GK + (KC) * 64 + c8 * 8);                 \
        }                                                                    \
    }

    G_FILL(0, 0);
    asm volatile("cp.async.commit_group;" ::: "memory");

    for (int it = 0; it < G_ITERS; it++) {
        const int buf = it & 1;
        asm volatile("cp.async.wait_group 0;" ::: "memory");
        __syncthreads();
        if (it + 1 < G_ITERS) {
            G_FILL(buf ^ 1, it + 1);
        }
        asm volatile("cp.async.commit_group;" ::: "memory");

        const __half* As = smh + buf * G_SH;
        const __half* Bs = As + G_AH;

#pragma unroll
        for (int ks = 0; ks < 4; ks++) {
            uint2 af[4][2];
            uint2 bf[4];
#pragma unroll
            for (int mt = 0; mt < 4; mt++) {
                int r = wm * 64 + mt * 16 + g;
                af[mt][0] = *(const uint2*)(As + r * G_P + ks * 16 + 4 * q);
                af[mt][1] = *(const uint2*)(As + (r + 8) * G_P + ks * 16 + 4 * q);
            }
#pragma unroll
            for (int nt = 0; nt < 4; nt++) {
                int c = wn * 32 + nt * 8 + g;
                bf[nt] = *(const uint2*)(Bs + c * G_P + ks * 16 + 4 * q);
            }
#pragma unroll
            for (int mt = 0; mt < 4; mt++)
#pragma unroll
                for (int nt = 0; nt < 4; nt++)
                    mma_f16(acc[mt][nt],
                            af[mt][0].x, af[mt][1].x,
                            af[mt][0].y, af[mt][1].y,
                            bf[nt].x,    bf[nt].y);
        }
    }
#undef G_FILL

#pragma unroll
    for (int mt = 0; mt < 4; mt++) {
        int m0 = bm * 128 + wm * 64 + mt * 16 + g;
        int m1 = m0 + 8;
#pragma unroll
        for (int nt = 0; nt < 4; nt++) {
            int n0 = bn * 128 + wn * 32 + nt * 8 + 2 * q;
            float b0 = bias[n0], b1 = bias[n0 + 1];
            float2 u0; u0.x = acc[mt][nt][0] + b0; u0.y = acc[mt][nt][1] + b1;
            *(float2*)&C[(size_t)m0 * GN + n0] = u0;
            float2 u1; u1.x = acc[mt][nt][2] + b0; u1.y = acc[mt][nt][3] + b1;
            *(float2*)&C[(size_t)m1 * GN + n0] = u1;
        }
    }
}

// ---------------------------------------------------------------------------
// Flash attention: CTA = 256 q-rows for one (b,h); warp owns 32 rows,
// processed as two 16-row halves sharing the staged K/V tile.
// K/V load + barrier cost per unit work halved vs 128-row version.
// ---------------------------------------------------------------------------
#define AP 80
#define A_TILEH (64 * AP)
#define A_KS0 0
#define A_VS0 A_TILEH
#define A_KS1 (2 * A_TILEH)
#define A_VS1 (3 * A_TILEH)
#define A_QS  (4 * A_TILEH)
#define ATTN_SMEM ((A_QS + 256 * AP) * 2)   // 81920 B

__global__ void __launch_bounds__(256, 2) attn_h_kernel(
    const __half* __restrict__ Q, const __half* __restrict__ K,
    const __half* __restrict__ Vt, __half* __restrict__ Y)
{
    extern __shared__ __half smha[];
    __half* Qs = smha + A_QS;

    const int tid  = threadIdx.x;
    const int lane = tid & 31;
    const int w    = tid >> 5;
    const int g    = lane >> 2;
    const int q    = lane & 3;
    const int qt   = (int)gridDim.x - 1 - (int)blockIdx.x;
    const int bh   = blockIdx.y;
    const int q0   = qt * 256;

    const int r0  = w * 32 + g;       // half-a rows
    const int r1  = r0 + 8;
    const int r2  = r0 + 16;          // half-b rows
    const int r3  = r0 + 24;
    const int gw0 = q0 + w * 32;      // warp's first global row

    const unsigned sb = (unsigned)__cvta_generic_to_shared(smha);
    const __half* Kb = K  + (size_t)bh * SEQ * HEAD_DIM;
    const __half* Vb = Vt + (size_t)bh * HEAD_DIM * SEQ;

#define A_FILL(S, K0)                                                        \
    {                                                                        \
        unsigned kba = sb + (unsigned)((S) ? A_KS1 : A_KS0) * 2u;            \
        unsigned vba = sb + (unsigned)((S) ? A_VS1 : A_VS0) * 2u;            \
        _Pragma("unroll")                                                    \
        for (int i = 0; i < 2; i++) {                                        \
            int idx = i * 256 + tid;                                         \
            int row = idx >> 3, c8 = idx & 7;                                \
            cpa16(kba + (unsigned)(row * AP + c8 * 8) * 2u,                  \
                  Kb + ((size_t)(K0) + row) * HEAD_DIM + c8 * 8);            \
            cpa16(vba + (unsigned)(row * AP + c8 * 8) * 2u,                  \
                  Vb + (size_t)row * SEQ + (K0) + c8 * 8);                   \
        }                                                                    \
    }

    {   // Q: 256 rows x 8 chunks of 8 halves = 2048 -> 8/thread
        const __half* Qp = Q + ((size_t)bh * SEQ + q0) * HEAD_DIM;
#pragma unroll
        for (int i = 0; i < 8; i++) {
            int idx = i * 256 + tid;
            int row = idx >> 3, c8 = idx & 7;
            *(uint4*)(Qs + row * AP + c8 * 8) =
                *(const uint4*)(Qp + row * HEAD_DIM + c8 * 8);
        }
    }

    float oa[8][4], ob[8][4];
#pragma unroll
    for (int nt = 0; nt < 8; nt++)
#pragma unroll
        for (int i = 0; i < 4; i++) { oa[nt][i] = 0.0f; ob[nt][i] = 0.0f; }
    float m0 = -1e30f, m1 = -1e30f, l0 = 0.0f, l1 = 0.0f;
    float m2 = -1e30f, m3 = -1e30f, l2 = 0.0f, l3 = 0.0f;

    const int kt_max = 4 * qt + 4;

    A_FILL(0, 0);
    asm volatile("cp.async.commit_group;" ::: "memory");

    for (int kt = 0; kt < kt_max; kt++) {
        const int buf = kt & 1;
        asm volatile("cp.async.wait_group 0;" ::: "memory");
        __syncthreads();
        if (kt + 1 < kt_max) {
            A_FILL(buf ^ 1, (kt + 1) * 64);
        }
        asm volatile("cp.async.commit_group;" ::: "memory");

        const __half* Ks = smha + (buf ? A_KS1 : A_KS0);
        const __half* Vs = smha + (buf ? A_VS1 : A_VS0);
        const int k0 = kt * 64;

        if (k0 > gw0 + 31) continue;   // warp fully above diagonal

        // ================= half A (rows r0, r1) =================
        if (k0 <= gw0 + 15) {
            float sc[8][4];
#pragma unroll
            for (int nt = 0; nt < 8; nt++)
#pragma unroll
                for (int i = 0; i < 4; i++) sc[nt][i] = 0.0f;

#pragma unroll
            for (int ks = 0; ks < 4; ks++) {
                uint2 a0 = *(const uint2*)(Qs + r0 * AP + ks * 16 + 4 * q);
                uint2 a1 = *(const uint2*)(Qs + r1 * AP + ks * 16 + 4 * q);
#pragma unroll
                for (int nt = 0; nt < 8; nt++) {
                    uint2 b = *(const uint2*)(Ks + (nt * 8 + g) * AP + ks * 16 + 4 * q);
                    mma_f16(sc[nt], a0.x, a1.x, a0.y, a1.y, b.x, b.y);
                }
            }

            if (k0 + 63 > gw0) {   // mask needed for half a
                int gr0 = q0 + r0, gr1 = q0 + r1;
#pragma unroll
                for (int nt = 0; nt < 8; nt++) {
                    int ck = k0 + nt * 8 + 2 * q;
                    if (ck     > gr0) sc[nt][0] = -1e30f;
                    if (ck + 1 > gr0) sc[nt][1] = -1e30f;
                    if (ck     > gr1) sc[nt][2] = -1e30f;
                    if (ck + 1 > gr1) sc[nt][3] = -1e30f;
                }
            }

            float rm0 = -1e30f, rm1 = -1e30f;
#pragma unroll
            for (int nt = 0; nt < 8; nt++) {
                rm0 = fmaxf(rm0, fmaxf(sc[nt][0], sc[nt][1]));
                rm1 = fmaxf(rm1, fmaxf(sc[nt][2], sc[nt][3]));
            }
            rm0 = fmaxf(rm0, __shfl_xor_sync(0xffffffffu, rm0, 1));
            rm0 = fmaxf(rm0, __shfl_xor_sync(0xffffffffu, rm0, 2));
            rm1 = fmaxf(rm1, __shfl_xor_sync(0xffffffffu, rm1, 1));
            rm1 = fmaxf(rm1, __shfl_xor_sync(0xffffffffu, rm1, 2));

            float nm0 = fmaxf(m0, rm0);
            float nm1 = fmaxf(m1, rm1);
            float cr0 = exp2f(m0 - nm0);
            float cr1 = exp2f(m1 - nm1);

            float s0 = 0.0f, s1 = 0.0f;
#pragma unroll
            for (int nt = 0; nt < 8; nt++) {
                sc[nt][0] = exp2f(sc[nt][0] - nm0);
                sc[nt][1] = exp2f(sc[nt][1] - nm0);
                sc[nt][2] = exp2f(sc[nt][2] - nm1);
                sc[nt][3] = exp2f(sc[nt][3] - nm1);
                s0 += sc[nt][0] + sc[nt][1];
                s1 += sc[nt][2] + sc[nt][3];
            }
            s0 += __shfl_xor_sync(0xffffffffu, s0, 1);
            s0 += __shfl_xor_sync(0xffffffffu, s0, 2);
            s1 += __shfl_xor_sync(0xffffffffu, s1, 1);
            s1 += __shfl_xor_sync(0xffffffffu, s1, 2);

            l0 = l0 * cr0 + s0;
            l1 = l1 * cr1 + s1;
            m0 = nm0; m1 = nm1;

#pragma unroll
            for (int nt = 0; nt < 8; nt++) {
                oa[nt][0] *= cr0; oa[nt][1] *= cr0;
                oa[nt][2] *= cr1; oa[nt][3] *= cr1;
            }

#pragma unroll
            for (int ks = 0; ks < 4; ks++) {
                unsigned pa0 = f2h2(sc[2*ks][0],     sc[2*ks][1]);
                unsigned pa1 = f2h2(sc[2*ks][2],     sc[2*ks][3]);
                unsigned pa2 = f2h2(sc[2*ks + 1][0], sc[2*ks + 1][1]);
                unsigned pa3 = f2h2(sc[2*ks + 1][2], sc[2*ks + 1][3]);
#pragma unroll
                for (int nt = 0; nt < 8; nt++) {
                    uint2 b = *(const uint2*)(Vs + (nt * 8 + g) * AP + ks * 16 + 4 * q);
                    mma_f16(oa[nt], pa0, pa1, pa2, pa3, b.x, b.y);
                }
            }
        }

        // ================= half B (rows r2, r3) =================
        {
            float sc[8][4];
#pragma unroll
            for (int nt = 0; nt < 8; nt++)
#pragma unroll
                for (int i = 0; i < 4; i++) sc[nt][i] = 0.0f;

#pragma unroll
            for (int ks = 0; ks < 4; ks++) {
                uint2 a0 = *(const uint2*)(Qs + r2 * AP + ks * 16 + 4 * q);
                uint2 a1 = *(const uint2*)(Qs + r3 * AP + ks * 16 + 4 * q);
#pragma unroll
                for (int nt = 0; nt < 8; nt++) {
                    uint2 b = *(const uint2*)(Ks + (nt * 8 + g) * AP + ks * 16 + 4 * q);
                    mma_f16(sc[nt], a0.x, a1.x, a0.y, a1.y, b.x, b.y);
                }
            }

            if (k0 + 63 > gw0 + 16) {   // mask needed for half b
                int gr2 = q0 + r2, gr3 = q0 + r3;
#pragma unroll
                for (int nt = 0; nt < 8; nt++) {
                    int ck = k0 + nt * 8 + 2 * q;
                    if (ck     > gr2) sc[nt][0] = -1e30f;
                    if (ck + 1 > gr2) sc[nt][1] = -1e30f;
                    if (ck     > gr3) sc[nt][2] = -1e30f;
                    if (ck + 1 > gr3) sc[nt][3] = -1e30f;
                }
            }

            float rm0 = -1e30f, rm1 = -1e30f;
#pragma unroll
            for (int nt = 0; nt < 8; nt++) {
                rm0 = fmaxf(rm0, fmaxf(sc[nt][0], sc[nt][1]));
                rm1 = fmaxf(rm1, fmaxf(sc[nt][2], sc[nt][3]));
            }
            rm0 = fmaxf(rm0, __shfl_xor_sync(0xffffffffu, rm0, 1));
            rm0 = fmaxf(rm0, __shfl_xor_sync(0xffffffffu, rm0, 2));
            rm1 = fmaxf(rm1, __shfl_xor_sync(0xffffffffu, rm1, 1));
            rm1 = fmaxf(rm1, __shfl_xor_sync(0xffffffffu, rm1, 2));

            float nm2 = fmaxf(m2, rm0);
            float nm3 = fmaxf(m3, rm1);
            float cr2 = exp2f(m2 - nm2);
            float cr3 = exp2f(m3 - nm3);

            float s0 = 0.0f, s1 = 0.0f;
#pragma unroll
            for (int nt = 0; nt < 8; nt++) {
                sc[nt][0] = exp2f(sc[nt][0] - nm2);
                sc[nt][1] = exp2f(sc[nt][1] - nm2);
                sc[nt][2] = exp2f(sc[nt][2] - nm3);
                sc[nt][3] = exp2f(sc[nt][3] - nm3);
                s0 += sc[nt][0] + sc[nt][1];
                s1 += sc[nt][2] + sc[nt][3];
            }
            s0 += __shfl_xor_sync(0xffffffffu, s0, 1);
            s0 += __shfl_xor_sync(0xffffffffu, s0, 2);
            s1 += __shfl_xor_sync(0xffffffffu, s1, 1);
            s1 += __shfl_xor_sync(0xffffffffu, s1, 2);

            l2 = l2 * cr2 + s0;
            l3 = l3 * cr3 + s1;
            m2 = nm2; m3 = nm3;

#pragma unroll
            for (int nt = 0; nt < 8; nt++) {
                ob[nt][0] *= cr2; ob[nt][1] *= cr2;
                ob[nt][2] *= cr3; ob[nt][3] *= cr3;
            }

#pragma unroll
            for (int ks = 0; ks < 4; ks++) {
                unsigned pa0 = f2h2(sc[2*ks][0],     sc[2*ks][1]);
                unsigned pa1 = f2h2(sc[2*ks][2],     sc[2*ks][3]);
                unsigned pa2 = f2h2(sc[2*ks + 1][0], sc[2*ks + 1][1]);
                unsigned pa3 = f2h2(sc[2*ks + 1][2], sc[2*ks + 1][3]);
#pragma unroll
                for (int nt = 0; nt < 8; nt++) {
                    uint2 b = *(const uint2*)(Vs + (nt * 8 + g) * AP + ks * 16 + 4 * q);
                    mma_f16(ob[nt], pa0, pa1, pa2, pa3, b.x, b.y);
                }
            }
        }
    }

    // ---- epilogue
    const int b = bh >> 4;
    const int h = bh & 15;
    const float i0 = 1.0f / l0, i1 = 1.0f / l1;
    const float i2 = 1.0f / l2, i3 = 1.0f / l3;
    __half* y0 = Y + ((size_t)b * SEQ + q0 + r0) * D_MODEL + h * HEAD_DIM;
    __half* y1 = Y + ((size_t)b * SEQ + q0 + r1) * D_MODEL + h * HEAD_DIM;
    __half* y2 = Y + ((size_t)b * SEQ + q0 + r2) * D_MODEL + h * HEAD_DIM;
    __half* y3 = Y + ((size_t)b * SEQ + q0 + r3) * D_MODEL + h * HEAD_DIM;
#pragma unroll
    for (int nt = 0; nt < 8; nt++) {
        int slot = (nt >> 1) * 16 + 4 * q + 2 * (nt & 1);
        *(unsigned*)(y0 + slot) = f2h2(oa[nt][0] * i0, oa[nt][1] * i0);
        *(unsigned*)(y1 + slot) = f2h2(oa[nt][2] * i1, oa[nt][3] * i1);
        *(unsigned*)(y2 + slot) = f2h2(ob[nt][0] * i2, ob[nt][1] * i2);
        *(unsigned*)(y3 + slot) = f2h2(ob[nt][2] * i3, ob[nt][3] * i3);
    }
#undef A_FILL
}

// ---------------------------------------------------------------------------
// Launch
// ---------------------------------------------------------------------------
extern "C" void kernel_launch(void* const* d_in, const int* in_sizes, int n_in,
                              void* d_out, int out_size)
{
    const float* x  = (const float*)d_in[0];
    const float* Wq = (const float*)d_in[1];
    const float* bq = (const float*)d_in[2];
    const float* Wk = (const float*)d_in[3];
    const float* bk = (const float*)d_in[4];
    const float* Wv = (const float*)d_in[5];
    const float* bv = (const float*)d_in[6];
    const float* Wo = (const float*)d_in[7];
    const float* bo = (const float*)d_in[8];
    float* out = (float*)d_out;

    __half *xt, *Wqt, *Wkt, *Wvt, *Wot, *Qb, *Kb, *Vb, *Yb;
    cudaGetSymbolAddress((void**)&xt,  g_xt);
    cudaGetSymbolAddress((void**)&Wqt, g_Wqt);
    cudaGetSymbolAddress((void**)&Wkt, g_Wkt);
    cudaGetSymbolAddress((void**)&Wvt, g_Wvt);
    cudaGetSymbolAddress((void**)&Wot, g_Wot);
    cudaGetSymbolAddress((void**)&Qb,  g_Q);
    cudaGetSymbolAddress((void**)&Kb,  g_K);
    cudaGetSymbolAddress((void**)&Vb,  g_Vt);
    cudaGetSymbolAddress((void**)&Yb,  g_Y);

    static bool attr_set = false;
    if (!attr_set) {
        cudaFuncSetAttribute(gemm_qkv_kernel,
                             cudaFuncAttributeMaxDynamicSharedMemorySize, Q_SMEM);
        cudaFuncSetAttribute(gemm_o_kernel,
                             cudaFuncAttributeMaxDynamicSharedMemorySize, G_SMEM);
        cudaFuncSetAttribute(attn_h_kernel,
                             cudaFuncAttributeMaxDynamicSharedMemorySize, ATTN_SMEM);
        attr_set = true;
    }

    const int TOT4 = XN4 + 4 * WN4;
    cvt_all_kernel<<<TOT4 / 256, 256>>>(
        (const float4*)x,  (unsigned*)xt,
        (const float4*)Wq, (unsigned*)Wqt,
        (const float4*)Wk, (unsigned*)Wkt,
        (const float4*)Wv, (unsigned*)Wvt,
        (const float4*)Wo, (unsigned*)Wot);

    dim3 qkvgrid(GN / 64, M_TOTAL / 128, 3);    // (16, 64, 3)
    gemm_qkv_kernel<<<qkvgrid, Q_THREADS, Q_SMEM>>>(
        xt, Wqt, bq, Qb, Wkt, bk, Kb, Wvt, bv, Vb);

    dim3 agrid(SEQ / 256, BATCH * N_HEADS);     // (8, 64)
    attn_h_kernel<<<agrid, 256, ATTN_SMEM>>>(Qb, Kb, Vb, Yb);

    dim3 ogrid(GN / 128, M_TOTAL / 128);        // (8, 64)
    gemm_o_kernel<<<ogrid, G_THREADS, G_SMEM>>>(Yb, Wot, bo, out);
}

// round 17
// speedup vs baseline: 1.0497x; 1.0497x over previous
#include <cuda_runtime.h>
#include <cuda_fp16.h>
#include <math.h>

#define D_MODEL  1024
#define N_HEADS  16
#define HEAD_DIM 64
#define BATCH    4
#define SEQ      2048
#define M_TOTAL  (BATCH * SEQ)   // 8192
#define GK 1024
#define GN 1024

// ---------------------------------------------------------------------------
// Scratch (fp16; k-dims stored permuted per 16-group: j=8h+2q+e -> 4q+2h+e)
// Wq pre-scaled by 0.125*log2(e): base-2 softmax with no scale multiply.
// ---------------------------------------------------------------------------
__device__ __align__(256) __half g_xt [(size_t)M_TOTAL * D_MODEL];
__device__ __align__(256) __half g_Wqt[(size_t)D_MODEL * D_MODEL];
__device__ __align__(256) __half g_Wkt[(size_t)D_MODEL * D_MODEL];
__device__ __align__(256) __half g_Wvt[(size_t)D_MODEL * D_MODEL];
__device__ __align__(256) __half g_Wot[(size_t)D_MODEL * D_MODEL];
__device__ __align__(256) __half g_Q  [(size_t)M_TOTAL * D_MODEL];  // [B,H,T,Dh] d-perm (pre-scaled)
__device__ __align__(256) __half g_K  [(size_t)M_TOTAL * D_MODEL];  // [B,H,T,Dh] d-perm
__device__ __align__(256) __half g_Vt [(size_t)M_TOTAL * D_MODEL];  // [B,H,Dh,T] t-perm
__device__ __align__(256) __half g_Y  [(size_t)M_TOTAL * D_MODEL];  // [B,T,D] D-perm

#define QSCALE (0.125f * 1.4426950408889634f)

// ---------------------------------------------------------------------------
// helpers
// ---------------------------------------------------------------------------
__device__ __forceinline__ unsigned f2h2(float lo, float hi) {
    __half2 h = __floats2half2_rn(lo, hi);
    return *(unsigned*)&h;
}
__device__ __forceinline__ unsigned short f2h(float v) {
    __half h = __float2half_rn(v);
    return *(unsigned short*)&h;
}

__device__ __forceinline__ void mma_f16(float c[4],
    unsigned a0, unsigned a1, unsigned a2, unsigned a3,
    unsigned b0, unsigned b1)
{
    asm volatile(
        "mma.sync.aligned.m16n8k16.row.col.f32.f16.f16.f32 "
        "{%0,%1,%2,%3}, {%4,%5,%6,%7}, {%8,%9}, {%0,%1,%2,%3};"
        : "+f"(c[0]), "+f"(c[1]), "+f"(c[2]), "+f"(c[3])
        : "r"(a0), "r"(a1), "r"(a2), "r"(a3), "r"(b0), "r"(b1));
}

__device__ __forceinline__ void cpa16(unsigned saddr, const void* gptr) {
    asm volatile("cp.async.cg.shared.global [%0], [%1], 16;"
                 :: "r"(saddr), "l"(gptr));
}

// ---------------------------------------------------------------------------
// fp32 -> fp16 + k-permute, fused over x + 4 weights (one launch).
// ---------------------------------------------------------------------------
#define XN4 (M_TOTAL * D_MODEL / 4)
#define WN4 (D_MODEL * D_MODEL / 4)

__device__ __forceinline__ void cvt_one(const float4* __restrict__ src,
                                        unsigned* __restrict__ dst, int i, float s)
{
    float4 v = src[i];
    int wi = i * 4;
    int h2 = ((wi & ~15) >> 1) + 2 * ((wi >> 1) & 3) + ((wi >> 3) & 1);
    dst[h2]     = f2h2(v.x * s, v.y * s);
    dst[h2 + 2] = f2h2(v.z * s, v.w * s);
}

__global__ void cvt_all_kernel(
    const float4* __restrict__ x,  unsigned* __restrict__ xt,
    const float4* __restrict__ w0, unsigned* __restrict__ t0,
    const float4* __restrict__ w1, unsigned* __restrict__ t1,
    const float4* __restrict__ w2, unsigned* __restrict__ t2,
    const float4* __restrict__ w3, unsigned* __restrict__ t3)
{
    int i = blockIdx.x * blockDim.x + threadIdx.x;
    if (i < XN4) { cvt_one(x, xt, i, 1.0f); return; }
    int j = i - XN4;
    int wsel = j >> 18;
    int r    = j & (WN4 - 1);
    if      (wsel == 0) cvt_one(w0, t0, r, QSCALE);
    else if (wsel == 1) cvt_one(w1, t1, r, 1.0f);
    else if (wsel == 2) cvt_one(w2, t2, r, 1.0f);
    else                cvt_one(w3, t3, r, 1.0f);
}

// ---------------------------------------------------------------------------
// QKV GEMM: BM=128, BN=64, BK=64; 128 threads = 4 warps (2m x 2n).
// 2-stage cp.async, single barrier per iter; 61.4 KB smem -> 3 CTAs/SM.
// ---------------------------------------------------------------------------
#define Q_P   80
#define Q_AH  (128 * Q_P)
#define Q_BH  (64 * Q_P)
#define Q_SH  (Q_AH + Q_BH)
#define Q_SMEM (2 * Q_SH * 2)
#define Q_ITERS (GK / 64)
#define Q_THREADS 128

__global__ void __launch_bounds__(Q_THREADS, 3) gemm_qkv_kernel(
    const __half* __restrict__ A,
    const __half* __restrict__ B0, const float* __restrict__ bias0, __half* __restrict__ C0,
    const __half* __restrict__ B1, const float* __restrict__ bias1, __half* __restrict__ C1,
    const __half* __restrict__ B2, const float* __restrict__ bias2, __half* __restrict__ C2)
{
    extern __shared__ __align__(128) __half smh[];
    const int z = blockIdx.z;
    const __half* B    = (z == 0) ? B0    : (z == 1) ? B1    : B2;
    const float* bias  = (z == 0) ? bias0 : (z == 1) ? bias1 : bias2;
    __half*      C     = (z == 0) ? C0    : (z == 1) ? C1    : C2;
    const float bscale = (z == 0) ? QSCALE : 1.0f;

    const int tid  = threadIdx.x;
    const int lane = tid & 31;
    const int w    = tid >> 5;
    const int wm   = w >> 1;
    const int wn   = w & 1;
    const int g    = lane >> 2;
    const int q    = lane & 3;
    const int bm   = blockIdx.y;
    const int bn   = blockIdx.x;

    const __half* Ab = A + (size_t)bm * 128 * GK;
    const __half* Bb = B + (size_t)bn * 64 * GK;
    const unsigned sb = (unsigned)__cvta_generic_to_shared(smh);

    float acc[4][4][4];
#pragma unroll
    for (int mt = 0; mt < 4; mt++)
#pragma unroll
        for (int nt = 0; nt < 4; nt++)
#pragma unroll
            for (int i = 0; i < 4; i++) acc[mt][nt][i] = 0.0f;

#define Q_FILL(S, KC)                                                        \
    {                                                                        \
        unsigned abase = sb + (unsigned)(S) * (Q_SH * 2);                    \
        unsigned bbase = abase + (Q_AH * 2);                                 \
        _Pragma("unroll")                                                    \
        for (int i = 0; i < 8; i++) {                                        \
            int idx = i * Q_THREADS + tid;                                   \
            int r = idx >> 3, c8 = idx & 7;                                  \
            cpa16(abase + (unsigned)(r * Q_P + c8 * 8) * 2u,                 \
                  Ab + (size_t)r * GK + (KC) * 64 + c8 * 8);                 \
        }                                                                    \
        _Pragma("unroll")                                                    \
        for (int i = 0; i < 4; i++) {                                        \
            int idx = i * Q_THREADS + tid;                                   \
            int r = idx >> 3, c8 = idx & 7;                                  \
            cpa16(bbase + (unsigned)(r * Q_P + c8 * 8) * 2u,                 \
                  Bb + (size_t)r * GK + (KC) * 64 + c8 * 8);                 \
        }                                                                    \
    }

    Q_FILL(0, 0);
    asm volatile("cp.async.commit_group;" ::: "memory");

    for (int it = 0; it < Q_ITERS; it++) {
        const int buf = it & 1;
        asm volatile("cp.async.wait_group 0;" ::: "memory");
        __syncthreads();
        if (it + 1 < Q_ITERS) {
            Q_FILL(buf ^ 1, it + 1);
        }
        asm volatile("cp.async.commit_group;" ::: "memory");

        const __half* As = smh + buf * Q_SH;
        const __half* Bs = As + Q_AH;

#pragma unroll
        for (int ks = 0; ks < 4; ks++) {
            uint2 af[4][2];
            uint2 bf[4];
#pragma unroll
            for (int mt = 0; mt < 4; mt++) {
                int r = wm * 64 + mt * 16 + g;
                af[mt][0] = *(const uint2*)(As + r * Q_P + ks * 16 + 4 * q);
                af[mt][1] = *(const uint2*)(As + (r + 8) * Q_P + ks * 16 + 4 * q);
            }
#pragma unroll
            for (int nt = 0; nt < 4; nt++) {
                int c = wn * 32 + nt * 8 + g;
                bf[nt] = *(const uint2*)(Bs + c * Q_P + ks * 16 + 4 * q);
            }
#pragma unroll
            for (int mt = 0; mt < 4; mt++)
#pragma unroll
                for (int nt = 0; nt < 4; nt++)
                    mma_f16(acc[mt][nt],
                            af[mt][0].x, af[mt][1].x,
                            af[mt][0].y, af[mt][1].y,
                            bf[nt].x,    bf[nt].y);
        }
    }
#undef Q_FILL

    const int h = bn;
#pragma unroll
    for (int mt = 0; mt < 4; mt++) {
        int m0 = bm * 128 + wm * 64 + mt * 16 + g;
        int m1 = m0 + 8;
        int bb0 = m0 / SEQ, t0 = m0 % SEQ;
        int bb1 = m1 / SEQ, t1 = m1 % SEQ;
#pragma unroll
        for (int nt = 0; nt < 4; nt++) {
            int nb = wn * 32 + nt * 8;
            int n0 = bn * 64 + nb + 2 * q;
            float b0 = bias[n0] * bscale, b1 = bias[n0 + 1] * bscale;
            float v00 = acc[mt][nt][0] + b0;
            float v01 = acc[mt][nt][1] + b1;
            float v10 = acc[mt][nt][2] + b0;
            float v11 = acc[mt][nt][3] + b1;
            if (z != 2) {
                int slot = (nb & ~15) + 4 * q + 2 * (nt & 1);
                size_t r0o = (((size_t)(bb0 * N_HEADS + h) * SEQ) + t0) * HEAD_DIM;
                size_t r1o = (((size_t)(bb1 * N_HEADS + h) * SEQ) + t1) * HEAD_DIM;
                *(unsigned*)(C + r0o + slot) = f2h2(v00, v01);
                *(unsigned*)(C + r1o + slot) = f2h2(v10, v11);
            } else {
                int d0 = nb + 2 * q;
                int t0p = (t0 & ~15) + 4 * (g >> 1) + (g & 1);
                int t1p = (t1 & ~15) + 4 * (g >> 1) + 2 + (g & 1);
                size_t base0 = ((size_t)(bb0 * N_HEADS + h) * HEAD_DIM + d0) * SEQ;
                size_t base1 = ((size_t)(bb1 * N_HEADS + h) * HEAD_DIM + d0) * SEQ;
                ((unsigned short*)C)[base0 + t0p]       = f2h(v00);
                ((unsigned short*)C)[base0 + SEQ + t0p] = f2h(v01);
                ((unsigned short*)C)[base1 + t1p]       = f2h(v10);
                ((unsigned short*)C)[base1 + SEQ + t1p] = f2h(v11);
            }
        }
    }
}

// ---------------------------------------------------------------------------
// O-proj GEMM: BM=128, BN=128, 256 threads, 2-stage, single barrier,
// 80 KB smem -> 2 CTAs/SM. fp32 [M,N] output.
// ---------------------------------------------------------------------------
#define G_P   80
#define G_AH  (128 * G_P)
#define G_BH  (128 * G_P)
#define G_SH  (G_AH + G_BH)
#define G_SMEM (2 * G_SH * 2)
#define G_ITERS (GK / 64)
#define G_THREADS 256

__global__ void __launch_bounds__(G_THREADS, 2) gemm_o_kernel(
    const __half* __restrict__ A, const __half* __restrict__ B,
    const float* __restrict__ bias, float* __restrict__ C)
{
    extern __shared__ __align__(128) __half smh[];

    const int tid  = threadIdx.x;
    const int lane = tid & 31;
    const int w    = tid >> 5;
    const int wm   = w >> 2;
    const int wn   = w & 3;
    const int g    = lane >> 2;
    const int q    = lane & 3;
    const int bm   = blockIdx.y;
    const int bn   = blockIdx.x;

    const __half* Ab = A + (size_t)bm * 128 * GK;
    const __half* Bb = B + (size_t)bn * 128 * GK;
    const unsigned sb = (unsigned)__cvta_generic_to_shared(smh);

    float acc[4][4][4];
#pragma unroll
    for (int mt = 0; mt < 4; mt++)
#pragma unroll
        for (int nt = 0; nt < 4; nt++)
#pragma unroll
            for (int i = 0; i < 4; i++) acc[mt][nt][i] = 0.0f;

#define G_FILL(S, KC)                                                        \
    {                                                                        \
        unsigned abase = sb + (unsigned)(S) * (G_SH * 2);                    \
        unsigned bbase = abase + (G_AH * 2);                                 \
        _Pragma("unroll")                                                    \
        for (int i = 0; i < 4; i++) {                                        \
            int idx = i * G_THREADS + tid;                                   \
            int r = idx >> 3, c8 = idx & 7;                                  \
            cpa16(abase + (unsigned)(r * G_P + c8 * 8) * 2u,                 \
                  Ab + (size_t)r * GK + (KC) * 64 + c8 * 8);                 \
        }                                                                    \
        _Pragma("unroll")                                                    \
        for (int i = 0; i < 4; i++) {                                        \
            int idx = i * G_THREADS + tid;                                   \
            int r = idx >> 3, c8 = idx & 7;                                  \
            cpa16(bbase + (unsigned)(r * G_P + c8 * 8) * 2u,                 \
                  Bb + (size_t)r * GK + (KC) * 64 + c8 * 8);                 \
        }                                                                    \
    }

    G_FILL(0, 0);
    asm volatile("cp.async.commit_group;" ::: "memory");

    for (int it = 0; it < G_ITERS; it++) {
        const int buf = it & 1;
        asm volatile("cp.async.wait_group 0;" ::: "memory");
        __syncthreads();
        if (it + 1 < G_ITERS) {
            G_FILL(buf ^ 1, it + 1);
        }
        asm volatile("cp.async.commit_group;" ::: "memory");

        const __half* As = smh + buf * G_SH;
        const __half* Bs = As + G_AH;

#pragma unroll
        for (int ks = 0; ks < 4; ks++) {
            uint2 af[4][2];
            uint2 bf[4];
#pragma unroll
            for (int mt = 0; mt < 4; mt++) {
                int r = wm * 64 + mt * 16 + g;
                af[mt][0] = *(const uint2*)(As + r * G_P + ks * 16 + 4 * q);
                af[mt][1] = *(const uint2*)(As + (r + 8) * G_P + ks * 16 + 4 * q);
            }
#pragma unroll
            for (int nt = 0; nt < 4; nt++) {
                int c = wn * 32 + nt * 8 + g;
                bf[nt] = *(const uint2*)(Bs + c * G_P + ks * 16 + 4 * q);
            }
#pragma unroll
            for (int mt = 0; mt < 4; mt++)
#pragma unroll
                for (int nt = 0; nt < 4; nt++)
                    mma_f16(acc[mt][nt],
                            af[mt][0].x, af[mt][1].x,
                            af[mt][0].y, af[mt][1].y,
                            bf[nt].x,    bf[nt].y);
        }
    }
#undef G_FILL

#pragma unroll
    for (int mt = 0; mt < 4; mt++) {
        int m0 = bm * 128 + wm * 64 + mt * 16 + g;
        int m1 = m0 + 8;
#pragma unroll
        for (int nt = 0; nt < 4; nt++) {
            int n0 = bn * 128 + wn * 32 + nt * 8 + 2 * q;
            float b0 = bias[n0], b1 = bias[n0 + 1];
            float2 u0; u0.x = acc[mt][nt][0] + b0; u0.y = acc[mt][nt][1] + b1;
            *(float2*)&C[(size_t)m0 * GN + n0] = u0;
            float2 u1; u1.x = acc[mt][nt][2] + b0; u1.y = acc[mt][nt][3] + b1;
            *(float2*)&C[(size_t)m1 * GN + n0] = u1;
        }
    }
}

// ---------------------------------------------------------------------------
// Flash attention: CTA = 128 q-rows (1024 CTAs, balance preserved),
// K-tile = 128 keys -> barriers/softmax updates per key HALVED vs R15.
// P in registers; K/V cp.async double buffer; single barrier per tile.
// K smem [128 key][64 d] pitch 80; V smem [64 d][128 key] pitch 136.
// ---------------------------------------------------------------------------
#define AKP 80
#define AVP 136
#define A_KTILE (128 * AKP)             // 10240 halves
#define A_VTILE (64 * AVP)              // 8704 halves
#define A_KS0 0
#define A_VS0 A_KTILE
#define A_KS1 (A_KTILE + A_VTILE)       // 18944
#define A_VS1 (A_KS1 + A_KTILE)        // 29184
#define A_QS  (A_KS1 + A_KTILE + A_VTILE)   // 37888
#define ATTN_SMEM ((A_QS + 128 * AKP) * 2)   // 96256 B

__global__ void __launch_bounds__(256, 2) attn_h_kernel(
    const __half* __restrict__ Q, const __half* __restrict__ K,
    const __half* __restrict__ Vt, __half* __restrict__ Y)
{
    extern __shared__ __half smha[];
    __half* Qs = smha + A_QS;

    const int tid  = threadIdx.x;
    const int lane = tid & 31;
    const int w    = tid >> 5;
    const int g    = lane >> 2;
    const int q    = lane & 3;
    const int qt   = (int)gridDim.x - 1 - (int)blockIdx.x;
    const int bh   = blockIdx.y;
    const int q0   = qt * 128;

    const int r0  = w * 16 + g;
    const int r1  = r0 + 8;
    const int gr0 = q0 + r0;
    const int gr1 = q0 + r1;

    const unsigned sb = (unsigned)__cvta_generic_to_shared(smha);
    const __half* Kb = K  + (size_t)bh * SEQ * HEAD_DIM;
    const __half* Vb = Vt + (size_t)bh * HEAD_DIM * SEQ;

    // stage 128-key K/V tile: K 128 rows x 8 chunks, V 64 rows x 16 chunks
#define A_FILL(S, K0)                                                        \
    {                                                                        \
        unsigned kba = sb + (unsigned)((S) ? A_KS1 : A_KS0) * 2u;            \
        unsigned vba = sb + (unsigned)((S) ? A_VS1 : A_VS0) * 2u;            \
        _Pragma("unroll")                                                    \
        for (int i = 0; i < 4; i++) {                                        \
            int idx = i * 256 + tid;                                         \
            int row = idx >> 3, c8 = idx & 7;                                \
            cpa16(kba + (unsigned)(row * AKP + c8 * 8) * 2u,                 \
                  Kb + ((size_t)(K0) + row) * HEAD_DIM + c8 * 8);            \
        }                                                                    \
        _Pragma("unroll")                                                    \
        for (int i = 0; i < 4; i++) {                                        \
            int idx = i * 256 + tid;                                         \
            int row = idx >> 4, c16 = idx & 15;                              \
            cpa16(vba + (unsigned)(row * AVP + c16 * 8) * 2u,                \
                  Vb + (size_t)row * SEQ + (K0) + c16 * 8);                  \
        }                                                                    \
    }

    {   // Q: 128 rows x 8 chunks of 8 halves
        const __half* Qp = Q + ((size_t)bh * SEQ + q0) * HEAD_DIM;
#pragma unroll
        for (int i = 0; i < 4; i++) {
            int idx = i * 256 + tid;
            int row = idx >> 3, c8 = idx & 7;
            *(uint4*)(Qs + row * AKP + c8 * 8) =
                *(const uint4*)(Qp + row * HEAD_DIM + c8 * 8);
        }
    }

    float o[8][4];
#pragma unroll
    for (int nt = 0; nt < 8; nt++)
#pragma unroll
        for (int i = 0; i < 4; i++) o[nt][i] = 0.0f;
    float m0 = -1e30f, m1 = -1e30f, l0 = 0.0f, l1 = 0.0f;

    const int kt_max = qt + 1;

    A_FILL(0, 0);
    asm volatile("cp.async.commit_group;" ::: "memory");

    for (int kt = 0; kt < kt_max; kt++) {
        const int buf = kt & 1;
        asm volatile("cp.async.wait_group 0;" ::: "memory");
        __syncthreads();
        if (kt + 1 < kt_max) {
            A_FILL(buf ^ 1, (kt + 1) * 128);
        }
        asm volatile("cp.async.commit_group;" ::: "memory");

        const __half* Ks = smha + (buf ? A_KS1 : A_KS0);
        const __half* Vs = smha + (buf ? A_VS1 : A_VS0);
        const int k0 = kt * 128;

        // ---- S2 = Q @ K^T over 128 keys (16 key-blocks of 8)
        float sc[16][4];
#pragma unroll
        for (int nt = 0; nt < 16; nt++)
#pragma unroll
            for (int i = 0; i < 4; i++) sc[nt][i] = 0.0f;

#pragma unroll
        for (int ks = 0; ks < 4; ks++) {
            uint2 a0 = *(const uint2*)(Qs + r0 * AKP + ks * 16 + 4 * q);
            uint2 a1 = *(const uint2*)(Qs + r1 * AKP + ks * 16 + 4 * q);
#pragma unroll
            for (int nt = 0; nt < 16; nt++) {
                uint2 b = *(const uint2*)(Ks + (nt * 8 + g) * AKP + ks * 16 + 4 * q);
                mma_f16(sc[nt], a0.x, a1.x, a0.y, a1.y, b.x, b.y);
            }
        }

        if (kt == qt) {   // diagonal tile: mask
#pragma unroll
            for (int nt = 0; nt < 16; nt++) {
                int ck = k0 + nt * 8 + 2 * q;
                if (ck     > gr0) sc[nt][0] = -1e30f;
                if (ck + 1 > gr0) sc[nt][1] = -1e30f;
                if (ck     > gr1) sc[nt][2] = -1e30f;
                if (ck + 1 > gr1) sc[nt][3] = -1e30f;
            }
        }

        // ---- warp-local online softmax (base 2), once per 128 keys
        float rm0 = -1e30f, rm1 = -1e30f;
#pragma unroll
        for (int nt = 0; nt < 16; nt++) {
            rm0 = fmaxf(rm0, fmaxf(sc[nt][0], sc[nt][1]));
            rm1 = fmaxf(rm1, fmaxf(sc[nt][2], sc[nt][3]));
        }
        rm0 = fmaxf(rm0, __shfl_xor_sync(0xffffffffu, rm0, 1));
        rm0 = fmaxf(rm0, __shfl_xor_sync(0xffffffffu, rm0, 2));
        rm1 = fmaxf(rm1, __shfl_xor_sync(0xffffffffu, rm1, 1));
        rm1 = fmaxf(rm1, __shfl_xor_sync(0xffffffffu, rm1, 2));

        float nm0 = fmaxf(m0, rm0);
        float nm1 = fmaxf(m1, rm1);
        float cr0 = exp2f(m0 - nm0);
        float cr1 = exp2f(m1 - nm1);

        float s0 = 0.0f, s1 = 0.0f;
#pragma unroll
        for (int nt = 0; nt < 16; nt++) {
            sc[nt][0] = exp2f(sc[nt][0] - nm0);
            sc[nt][1] = exp2f(sc[nt][1] - nm0);
            sc[nt][2] = exp2f(sc[nt][2] - nm1);
            sc[nt][3] = exp2f(sc[nt][3] - nm1);
            s0 += sc[nt][0] + sc[nt][1];
            s1 += sc[nt][2] + sc[nt][3];
        }
        s0 += __shfl_xor_sync(0xffffffffu, s0, 1);
        s0 += __shfl_xor_sync(0xffffffffu, s0, 2);
        s1 += __shfl_xor_sync(0xffffffffu, s1, 1);
        s1 += __shfl_xor_sync(0xffffffffu, s1, 2);

        l0 = l0 * cr0 + s0;
        l1 = l1 * cr1 + s1;
        m0 = nm0; m1 = nm1;

#pragma unroll
        for (int nt = 0; nt < 8; nt++) {
            o[nt][0] *= cr0; o[nt][1] *= cr0;
            o[nt][2] *= cr1; o[nt][3] *= cr1;
        }

        // ---- O += P @ V : P from registers; 8 k16-steps over 128 keys
#pragma unroll
        for (int ks = 0; ks < 8; ks++) {
            unsigned pa0 = f2h2(sc[2*ks][0],     sc[2*ks][1]);
            unsigned pa1 = f2h2(sc[2*ks][2],     sc[2*ks][3]);
            unsigned pa2 = f2h2(sc[2*ks + 1][0], sc[2*ks + 1][1]);
            unsigned pa3 = f2h2(sc[2*ks + 1][2], sc[2*ks + 1][3]);
#pragma unroll
            for (int nt = 0; nt < 8; nt++) {
                uint2 b = *(const uint2*)(Vs + (nt * 8 + g) * AVP + ks * 16 + 4 * q);
                mma_f16(o[nt], pa0, pa1, pa2, pa3, b.x, b.y);
            }
        }
    }

    const float inv0 = 1.0f / l0;
    const float inv1 = 1.0f / l1;
    const int b = bh >> 4;
    const int h = bh & 15;
    __half* y0 = Y + ((size_t)b * SEQ + gr0) * D_MODEL + h * HEAD_DIM;
    __half* y1 = Y + ((size_t)b * SEQ + gr1) * D_MODEL + h * HEAD_DIM;
#pragma unroll
    for (int nt = 0; nt < 8; nt++) {
        int slot = (nt >> 1) * 16 + 4 * q + 2 * (nt & 1);
        *(unsigned*)(y0 + slot) = f2h2(o[nt][0] * inv0, o[nt][1] * inv0);
        *(unsigned*)(y1 + slot) = f2h2(o[nt][2] * inv1, o[nt][3] * inv1);
    }
#undef A_FILL
}

// ---------------------------------------------------------------------------
// Launch
// ---------------------------------------------------------------------------
extern "C" void kernel_launch(void* const* d_in, const int* in_sizes, int n_in,
                              void* d_out, int out_size)
{
    const float* x  = (const float*)d_in[0];
    const float* Wq = (const float*)d_in[1];
    const float* bq = (const float*)d_in[2];
    const float* Wk = (const float*)d_in[3];
    const float* bk = (const float*)d_in[4];
    const float* Wv = (const float*)d_in[5];
    const float* bv = (const float*)d_in[6];
    const float* Wo = (const float*)d_in[7];
    const float* bo = (const float*)d_in[8];
    float* out = (float*)d_out;

    __half *xt, *Wqt, *Wkt, *Wvt, *Wot, *Qb, *Kb, *Vb, *Yb;
    cudaGetSymbolAddress((void**)&xt,  g_xt);
    cudaGetSymbolAddress((void**)&Wqt, g_Wqt);
    cudaGetSymbolAddress((void**)&Wkt, g_Wkt);
    cudaGetSymbolAddress((void**)&Wvt, g_Wvt);
    cudaGetSymbolAddress((void**)&Wot, g_Wot);
    cudaGetSymbolAddress((void**)&Qb,  g_Q);
    cudaGetSymbolAddress((void**)&Kb,  g_K);
    cudaGetSymbolAddress((void**)&Vb,  g_Vt);
    cudaGetSymbolAddress((void**)&Yb,  g_Y);

    static bool attr_set = false;
    if (!attr_set) {
        cudaFuncSetAttribute(gemm_qkv_kernel,
                             cudaFuncAttributeMaxDynamicSharedMemorySize, Q_SMEM);
        cudaFuncSetAttribute(gemm_o_kernel,
                             cudaFuncAttributeMaxDynamicSharedMemorySize, G_SMEM);
        cudaFuncSetAttribute(attn_h_kernel,
                             cudaFuncAttributeMaxDynamicSharedMemorySize, ATTN_SMEM);
        attr_set = true;
    }

    const int TOT4 = XN4 + 4 * WN4;
    cvt_all_kernel<<<TOT4 / 256, 256>>>(
        (const float4*)x,  (unsigned*)xt,
        (const float4*)Wq, (unsigned*)Wqt,
        (const float4*)Wk, (unsigned*)Wkt,
        (const float4*)Wv, (unsigned*)Wvt,
        (const float4*)Wo, (unsigned*)Wot);

    dim3 qkvgrid(GN / 64, M_TOTAL / 128, 3);    // (16, 64, 3)
    gemm_qkv_kernel<<<qkvgrid, Q_THREADS, Q_SMEM>>>(
        xt, Wqt, bq, Qb, Wkt, bk, Kb, Wvt, bv, Vb);

    dim3 agrid(SEQ / 128, BATCH * N_HEADS);     // (16, 64)
    attn_h_kernel<<<agrid, 256, ATTN_SMEM>>>(Qb, Kb, Vb, Yb);

    dim3 ogrid(GN / 128, M_TOTAL / 128);        // (8, 64)
    gemm_o_kernel<<<ogrid, G_THREADS, G_SMEM>>>(Yb, Wot, bo, out);
}